// round 10
// baseline (speedup 1.0000x reference)
#include <cuda_runtime.h>
#include <cstdint>
#include <cstddef>

#define FIN   256
#define NHID  64
#define MAXN  50176
#define MAXE  800064

// ---------------- scratch (static device memory; no allocations) ----------------
__device__ float  g_xw[(size_t)3 * MAXN * NHID];  // x @ W1 per view  [v][n][64]
__device__ float  g_deg[3 * MAXN];                // weighted in-degree (no self loop; +1 at norm)
__device__ float2 g_dinv[3 * MAXN];               // (rsqrt(deg+1), rsqrt(count+1))
__device__ float2 g_hw2[3 * MAXN];                // (h @ W2, dinv2) per node per view
__device__ int    g_ecnt[3 * MAXN];               // in-edge counts
__device__ int    g_wptr[3 * MAXN];               // CSR fill cursors (absolute)
__device__ int    g_rowstart[3 * (MAXN + 1)];     // CSR row offsets
__device__ int    g_part[3 * 64];                 // scan partials
__device__ int2   g_ed1[(size_t)3 * MAXE];        // packed (src, c1 bits) per CSR slot

// ---------------- init: zero counters ----------------
__global__ void k_init(int N) {
    int n = blockIdx.x * 256 + threadIdx.x;
    int v = blockIdx.y;
    if (n < N) {
        g_deg[v * MAXN + n]  = 0.0f;
        g_ecnt[v * MAXN + n] = 0;
    }
}

// ---------------- GEMM: xw[v] = X[N,256] @ W1_v[256,64] (tf32 mma.sync) --------
__device__ __forceinline__ unsigned f2tf(float f) {
    unsigned r;
    asm("cvt.rna.tf32.f32 %0, %1;" : "=r"(r) : "f"(f));
    return r;
}

__global__ __launch_bounds__(256) void k_gemm(
    const float* __restrict__ X,
    const float* __restrict__ Wa, const float* __restrict__ Wb, const float* __restrict__ Wc,
    int N)
{
    __shared__ __align__(16) float As[128 * 36];  // 128 rows x 32 k (pad 36)
    __shared__ __align__(16) float Bs[32 * 72];   // 32 k x 64 cols (pad 72)

    const float* W = (blockIdx.y == 0) ? Wa : ((blockIdx.y == 1) ? Wb : Wc);
    int row0 = blockIdx.x * 128;
    int tid  = threadIdx.x;
    int lane = tid & 31, warp = tid >> 5;
    int wr = warp >> 1;   // 0..3 : 32-row group
    int wc = warp & 1;    // 0..1 : 32-col group

    float acc[2][4][4];
#pragma unroll
    for (int a = 0; a < 2; a++)
#pragma unroll
        for (int b = 0; b < 4; b++)
#pragma unroll
            for (int c = 0; c < 4; c++) acc[a][b][c] = 0.f;

    for (int kc = 0; kc < FIN; kc += 32) {
        {
            int c = (tid & 7) * 4;
#pragma unroll
            for (int it = 0; it < 4; it++) {
                int r = (tid >> 3) + it * 32;
                int gr = row0 + r;
                float4 val = make_float4(0.f, 0.f, 0.f, 0.f);
                if (gr < N) val = *reinterpret_cast<const float4*>(X + (size_t)gr * FIN + kc + c);
                val.x = __uint_as_float(f2tf(val.x));
                val.y = __uint_as_float(f2tf(val.y));
                val.z = __uint_as_float(f2tf(val.z));
                val.w = __uint_as_float(f2tf(val.w));
                *reinterpret_cast<float4*>(&As[r * 36 + c]) = val;
            }
        }
        {
            int c = (tid & 15) * 4;
#pragma unroll
            for (int it = 0; it < 2; it++) {
                int k = (tid >> 4) + it * 16;
                float4 val = *reinterpret_cast<const float4*>(W + (size_t)(kc + k) * NHID + c);
                val.x = __uint_as_float(f2tf(val.x));
                val.y = __uint_as_float(f2tf(val.y));
                val.z = __uint_as_float(f2tf(val.z));
                val.w = __uint_as_float(f2tf(val.w));
                *reinterpret_cast<float4*>(&Bs[k * 72 + c]) = val;
            }
        }
        __syncthreads();

#pragma unroll
        for (int ks = 0; ks < 4; ks++) {
            int kb = ks * 8;
            unsigned a[2][4];
            int ar = wr * 32 + (lane >> 2);
            int ak = kb + (lane & 3);
#pragma unroll
            for (int t = 0; t < 2; t++) {
                a[t][0] = __float_as_uint(As[(ar + t * 16) * 36 + ak]);
                a[t][1] = __float_as_uint(As[(ar + t * 16 + 8) * 36 + ak]);
                a[t][2] = __float_as_uint(As[(ar + t * 16) * 36 + ak + 4]);
                a[t][3] = __float_as_uint(As[(ar + t * 16 + 8) * 36 + ak + 4]);
            }
#pragma unroll
            for (int ct = 0; ct < 4; ct++) {
                int j = wc * 32 + ct * 8 + (lane >> 2);
                unsigned b0 = __float_as_uint(Bs[(kb + (lane & 3)) * 72 + j]);
                unsigned b1 = __float_as_uint(Bs[(kb + (lane & 3) + 4) * 72 + j]);
#pragma unroll
                for (int t = 0; t < 2; t++) {
                    asm volatile(
                        "mma.sync.aligned.m16n8k8.row.col.f32.tf32.tf32.f32 "
                        "{%0,%1,%2,%3}, {%4,%5,%6,%7}, {%8,%9}, {%0,%1,%2,%3};"
                        : "+f"(acc[t][ct][0]), "+f"(acc[t][ct][1]),
                          "+f"(acc[t][ct][2]), "+f"(acc[t][ct][3])
                        : "r"(a[t][0]), "r"(a[t][1]), "r"(a[t][2]), "r"(a[t][3]),
                          "r"(b0), "r"(b1));
                }
            }
        }
        __syncthreads();
    }

    float* xwv = g_xw + (size_t)blockIdx.y * MAXN * NHID;
#pragma unroll
    for (int t = 0; t < 2; t++) {
        int rb = row0 + wr * 32 + t * 16 + (lane >> 2);
#pragma unroll
        for (int ct = 0; ct < 4; ct++) {
            int col = wc * 32 + ct * 8 + (lane & 3) * 2;
            if (rb < N)
                *reinterpret_cast<float2*>(&xwv[(size_t)rb * NHID + col]) =
                    make_float2(acc[t][ct][0], acc[t][ct][1]);
            if (rb + 8 < N)
                *reinterpret_cast<float2*>(&xwv[(size_t)(rb + 8) * NHID + col]) =
                    make_float2(acc[t][ct][2], acc[t][ct][3]);
        }
    }
}

// ---------------- degree accumulation ----------------
__global__ void k_deg(const int* __restrict__ e0, const int* __restrict__ e1,
                      const int* __restrict__ e2,
                      const float* __restrict__ w0, const float* __restrict__ w1,
                      const float* __restrict__ w2, int E)
{
    int e = blockIdx.x * 256 + threadIdx.x;
    if (e >= E) return;
    int v = blockIdx.y;
    const int* ei = (v == 0) ? e0 : ((v == 1) ? e1 : e2);
    const float* ew = (v == 0) ? w0 : ((v == 1) ? w1 : w2);
    int dst = ei[E + e];
    atomicAdd(&g_deg[v * MAXN + dst], ew[e]);
    atomicAdd(&g_ecnt[v * MAXN + dst], 1);
}

// ---------------- 3-phase parallel exclusive scan (coalesced, full-chip) -------
__global__ __launch_bounds__(1024) void k_scanA(int N) {
    int v = blockIdx.y;
    int i = blockIdx.x * 1024 + threadIdx.x;
    int val = (i < N) ? g_ecnt[v * MAXN + i] : 0;
#pragma unroll
    for (int o = 16; o; o >>= 1) val += __shfl_xor_sync(0xffffffffu, val, o);
    __shared__ int ws[32];
    int lane = threadIdx.x & 31, wid = threadIdx.x >> 5;
    if (lane == 0) ws[wid] = val;
    __syncthreads();
    if (wid == 0) {
        int s = ws[lane];
#pragma unroll
        for (int o = 16; o; o >>= 1) s += __shfl_xor_sync(0xffffffffu, s, o);
        if (lane == 0) g_part[v * 64 + blockIdx.x] = s;
    }
}

__global__ void k_scanB(int nchunk, int N, int E) {
    int v = blockIdx.x;
    int t = threadIdx.x;                       // 64 threads
    int val = (t < nchunk) ? g_part[v * 64 + t] : 0;
    int inc = val;
    int lane = t & 31, wid = t >> 5;
#pragma unroll
    for (int o = 1; o < 32; o <<= 1) {
        int x = __shfl_up_sync(0xffffffffu, inc, o);
        if (lane >= o) inc += x;
    }
    __shared__ int tot;
    if (wid == 0 && lane == 31) tot = inc;
    __syncthreads();
    if (wid == 1) inc += tot;
    g_part[v * 64 + t] = inc - val;            // exclusive
    if (t == 0) g_rowstart[v * (MAXN + 1) + N] = E;
}

// scanC fused with normalizer computation + cursor init
__global__ __launch_bounds__(1024) void k_scanC(int N) {
    int v = blockIdx.y;
    int i = blockIdx.x * 1024 + threadIdx.x;
    int val = (i < N) ? g_ecnt[v * MAXN + i] : 0;
    int lane = threadIdx.x & 31, wid = threadIdx.x >> 5;
    int inc = val;
#pragma unroll
    for (int o = 1; o < 32; o <<= 1) {
        int x = __shfl_up_sync(0xffffffffu, inc, o);
        if (lane >= o) inc += x;
    }
    __shared__ int ws[32];
    if (lane == 31) ws[wid] = inc;
    __syncthreads();
    if (wid == 0) {
        int s = ws[lane];
        int sinc = s;
#pragma unroll
        for (int o = 1; o < 32; o <<= 1) {
            int x = __shfl_up_sync(0xffffffffu, sinc, o);
            if (lane >= o) sinc += x;
        }
        ws[lane] = sinc - s;
    }
    __syncthreads();
    int ex = inc - val + ws[wid] + g_part[v * 64 + blockIdx.x];
    if (i < N) {
        g_rowstart[v * (MAXN + 1) + i] = ex;
        g_wptr[v * MAXN + i] = ex;                        // absolute cursor
        float2 dv;
        dv.x = rsqrtf(g_deg[v * MAXN + i] + 1.0f);        // conv1: weighted deg + self loop
        dv.y = rsqrtf((float)(val + 1));                  // conv2: unit weights + self loop
        g_dinv[v * MAXN + i] = dv;
    }
}

// ---------------- CSR fill (counting-sort placement + packed edge records) -----
__global__ void k_fill(const int* __restrict__ e0, const int* __restrict__ e1,
                       const int* __restrict__ e2,
                       const float* __restrict__ w0, const float* __restrict__ w1,
                       const float* __restrict__ w2, int E)
{
    int e = blockIdx.x * 256 + threadIdx.x;
    if (e >= E) return;
    int v = blockIdx.y;
    const int* ei = (v == 0) ? e0 : ((v == 1) ? e1 : e2);
    const float* ew = (v == 0) ? w0 : ((v == 1) ? w1 : w2);
    int src = ei[e];
    int dst = ei[E + e];
    float w = ew[e];
    float ds = g_dinv[v * MAXN + src].x;
    float dd = g_dinv[v * MAXN + dst].x;
    int pos = atomicAdd(&g_wptr[v * MAXN + dst], 1);
    g_ed1[(size_t)v * MAXE + pos] = make_int2(src, __float_as_int(ds * w * dd));
}

// ---------------- conv1 aggregate + relu + feature sum + h@W2 (warp per node) --
__global__ __launch_bounds__(256) void k_agg(
    const float* __restrict__ b1a, const float* __restrict__ b1b, const float* __restrict__ b1c,
    const float* __restrict__ w2a, const float* __restrict__ w2b, const float* __restrict__ w2c,
    float* __restrict__ out, int N)
{
    int n = (blockIdx.x * 256 + threadIdx.x) >> 5;
    int lane = threadIdx.x & 31;
    if (n >= N) return;

    float2 f = make_float2(0.f, 0.f);
#pragma unroll
    for (int v = 0; v < 3; v++) {
        const float2* b1 = reinterpret_cast<const float2*>((v == 0) ? b1a : ((v == 1) ? b1b : b1c));
        const float2* w2 = reinterpret_cast<const float2*>((v == 0) ? w2a : ((v == 1) ? w2b : w2c));
        const float2* xw2 = reinterpret_cast<const float2*>(g_xw + (size_t)v * MAXN * NHID);
        float2 dvn = g_dinv[v * MAXN + n];
        float selfc = dvn.x * dvn.x;
        float2 a = xw2[(size_t)n * 32 + lane];
        a.x *= selfc; a.y *= selfc;

        int p  = g_rowstart[v * (MAXN + 1) + n];
        int pe = g_rowstart[v * (MAXN + 1) + n + 1];
        const int2* ed = g_ed1 + (size_t)v * MAXE;

        // software-pipelined 4-way gather-accumulate:
        // next group's records load while current group's row gathers are in flight
        if (p + 3 < pe) {
            int2 e0 = ed[p], e1 = ed[p + 1], e2 = ed[p + 2], e3 = ed[p + 3];
            while (true) {
                float2 x0 = xw2[(size_t)e0.x * 32 + lane];
                float2 x1 = xw2[(size_t)e1.x * 32 + lane];
                float2 x2 = xw2[(size_t)e2.x * 32 + lane];
                float2 x3 = xw2[(size_t)e3.x * 32 + lane];
                int np = p + 4;
                bool nh = (np + 3 < pe);
                int2 f0, f1, f2, f3;
                if (nh) { f0 = ed[np]; f1 = ed[np + 1]; f2 = ed[np + 2]; f3 = ed[np + 3]; }
                float c0 = __int_as_float(e0.y), c1 = __int_as_float(e1.y);
                float c2 = __int_as_float(e2.y), c3 = __int_as_float(e3.y);
                a.x = fmaf(x0.x, c0, a.x); a.y = fmaf(x0.y, c0, a.y);
                a.x = fmaf(x1.x, c1, a.x); a.y = fmaf(x1.y, c1, a.y);
                a.x = fmaf(x2.x, c2, a.x); a.y = fmaf(x2.y, c2, a.y);
                a.x = fmaf(x3.x, c3, a.x); a.y = fmaf(x3.y, c3, a.y);
                p = np;
                if (!nh) break;
                e0 = f0; e1 = f1; e2 = f2; e3 = f3;
            }
        }
        for (; p < pe; p++) {
            int2 e0 = ed[p];
            float2 x0 = xw2[(size_t)e0.x * 32 + lane];
            float c0 = __int_as_float(e0.y);
            a.x = fmaf(x0.x, c0, a.x); a.y = fmaf(x0.y, c0, a.y);
        }

        float2 bb = b1[lane];
        float h0 = fmaxf(a.x + bb.x, 0.f);
        float h1 = fmaxf(a.y + bb.y, 0.f);
        f.x += h0; f.y += h1;
        float2 wv = w2[lane];
        float hw = h0 * wv.x + h1 * wv.y;
#pragma unroll
        for (int o = 16; o; o >>= 1) hw += __shfl_xor_sync(0xffffffffu, hw, o);
        if (lane == 0) g_hw2[v * MAXN + n] = make_float2(hw, dvn.y);
    }
    float2* fo = reinterpret_cast<float2*>(out + N + (size_t)n * NHID);
    fo[lane] = f;
}

// ---------------- conv2 aggregate -> x_flat (8-lane subgroup per node) ---------
__global__ __launch_bounds__(256) void k_out(
    const float* __restrict__ b2a, const float* __restrict__ b2b, const float* __restrict__ b2c,
    float* __restrict__ out, int N)
{
    int t = blockIdx.x * 256 + threadIdx.x;
    int n  = t >> 3;           // node per 8-lane subgroup
    int li = t & 7;            // lane within subgroup
    if (n >= N) return;

    float total = 0.f;
#pragma unroll
    for (int v = 0; v < 3; v++) {
        int p0 = g_rowstart[v * (MAXN + 1) + n];
        int p1 = g_rowstart[v * (MAXN + 1) + n + 1];
        const int2* ed = g_ed1 + (size_t)v * MAXE;
        float acc = 0.f;
        for (int p = p0 + li; p < p1; p += 8) {
            float2 hd = g_hw2[v * MAXN + ed[p].x];   // (hw, dinv2) one gather
            acc += hd.x * hd.y;
        }
#pragma unroll
        for (int o = 4; o; o >>= 1) acc += __shfl_xor_sync(0xffffffffu, acc, o);
        if (li == 0) {
            float2 sv = g_hw2[v * MAXN + n];
            const float* b2 = (v == 0) ? b2a : ((v == 1) ? b2b : b2c);
            total += sv.y * (acc + sv.y * sv.x) + b2[0];
        }
    }
    if (li == 0) out[n] = total;
}

// ---------------- launch ----------------
extern "C" void kernel_launch(void* const* d_in, const int* in_sizes, int n_in,
                              void* d_out, int out_size)
{
    const float* x = (const float*)d_in[0];
    const int* ei0 = (const int*)d_in[1];
    const int* ei1 = (const int*)d_in[2];
    const int* ei2 = (const int*)d_in[3];
    const float* ew0 = (const float*)d_in[4];
    const float* ew1 = (const float*)d_in[5];
    const float* ew2 = (const float*)d_in[6];
    const float* W1a = (const float*)d_in[7];
    const float* b1a = (const float*)d_in[8];
    const float* W2a = (const float*)d_in[9];
    const float* b2a = (const float*)d_in[10];
    const float* W1b = (const float*)d_in[11];
    const float* b1b = (const float*)d_in[12];
    const float* W2b = (const float*)d_in[13];
    const float* b2b = (const float*)d_in[14];
    const float* W1c = (const float*)d_in[15];
    const float* b1c = (const float*)d_in[16];
    const float* W2c = (const float*)d_in[17];
    const float* b2c = (const float*)d_in[18];

    int N = in_sizes[0] / FIN;
    int E = in_sizes[1] / 2;
    float* out = (float*)d_out;

    int nb_n = (N + 255) / 256;
    int eb   = (E + 255) / 256;
    int nchunk = (N + 1023) / 1024;

    k_init<<<dim3(nb_n, 3), 256>>>(N);
    k_gemm<<<dim3((N + 127) / 128, 3), 256>>>(x, W1a, W1b, W1c, N);
    k_deg<<<dim3(eb, 3), 256>>>(ei0, ei1, ei2, ew0, ew1, ew2, E);
    k_scanA<<<dim3(nchunk, 3), 1024>>>(N);
    k_scanB<<<3, 64>>>(nchunk, N, E);
    k_scanC<<<dim3(nchunk, 3), 1024>>>(N);
    k_fill<<<dim3(eb, 3), 256>>>(ei0, ei1, ei2, ew0, ew1, ew2, E);
    k_agg<<<(N + 7) / 8, 256>>>(b1a, b1b, b1c, W2a, W2b, W2c, out, N);
    k_out<<<(N * 8 + 255) / 256, 256>>>(b2a, b2b, b2c, out, N);
}

// round 15
// speedup vs baseline: 1.3023x; 1.3023x over previous
#include <cuda_runtime.h>
#include <cstdint>
#include <cstddef>

#define FIN   256
#define NHID  64
#define MAXN  50176
#define MAXE  800064

// ---------------- scratch (static device memory; no allocations) ----------------
__device__ float  g_xw[(size_t)3 * MAXN * NHID];  // x @ W1 per view  [v][n][64]
__device__ float  g_deg[3 * MAXN];                // weighted in-degree (no self loop; +1 at norm)
__device__ float2 g_dinv[3 * MAXN];               // (rsqrt(deg+1), rsqrt(count+1))
__device__ float2 g_hw2[3 * MAXN];                // (h @ W2, dinv2) per node per view
__device__ int    g_ecnt[3 * MAXN];               // in-edge counts
__device__ int    g_wptr[3 * MAXN];               // CSR fill cursors (absolute)
__device__ int    g_rowstart[3 * (MAXN + 1)];     // CSR row offsets
__device__ int    g_part[3 * 64];                 // scan partials
__device__ int2   g_ed1[(size_t)3 * MAXE];        // packed (src, c1 bits) per CSR slot

// ---------------- init: zero counters ----------------
__global__ void k_init(int N) {
    int n = blockIdx.x * 256 + threadIdx.x;
    int v = blockIdx.y;
    if (n < N) {
        g_deg[v * MAXN + n]  = 0.0f;
        g_ecnt[v * MAXN + n] = 0;
    }
}

// ---------------- GEMM: xw[v] = X[N,256] @ W1_v[256,64] (tf32 mma.sync) --------
__device__ __forceinline__ unsigned f2tf(float f) {
    unsigned r;
    asm("cvt.rna.tf32.f32 %0, %1;" : "=r"(r) : "f"(f));
    return r;
}

__global__ __launch_bounds__(256) void k_gemm(
    const float* __restrict__ X,
    const float* __restrict__ Wa, const float* __restrict__ Wb, const float* __restrict__ Wc,
    int N)
{
    __shared__ __align__(16) float As[128 * 36];  // 128 rows x 32 k (pad 36)
    __shared__ __align__(16) float Bs[32 * 72];   // 32 k x 64 cols (pad 72)

    const float* W = (blockIdx.y == 0) ? Wa : ((blockIdx.y == 1) ? Wb : Wc);
    int row0 = blockIdx.x * 128;
    int tid  = threadIdx.x;
    int lane = tid & 31, warp = tid >> 5;
    int wr = warp >> 1;   // 0..3 : 32-row group
    int wc = warp & 1;    // 0..1 : 32-col group

    float acc[2][4][4];
#pragma unroll
    for (int a = 0; a < 2; a++)
#pragma unroll
        for (int b = 0; b < 4; b++)
#pragma unroll
            for (int c = 0; c < 4; c++) acc[a][b][c] = 0.f;

    for (int kc = 0; kc < FIN; kc += 32) {
        {
            int c = (tid & 7) * 4;
#pragma unroll
            for (int it = 0; it < 4; it++) {
                int r = (tid >> 3) + it * 32;
                int gr = row0 + r;
                float4 val = make_float4(0.f, 0.f, 0.f, 0.f);
                if (gr < N) val = *reinterpret_cast<const float4*>(X + (size_t)gr * FIN + kc + c);
                val.x = __uint_as_float(f2tf(val.x));
                val.y = __uint_as_float(f2tf(val.y));
                val.z = __uint_as_float(f2tf(val.z));
                val.w = __uint_as_float(f2tf(val.w));
                *reinterpret_cast<float4*>(&As[r * 36 + c]) = val;
            }
        }
        {
            int c = (tid & 15) * 4;
#pragma unroll
            for (int it = 0; it < 2; it++) {
                int k = (tid >> 4) + it * 16;
                float4 val = *reinterpret_cast<const float4*>(W + (size_t)(kc + k) * NHID + c);
                val.x = __uint_as_float(f2tf(val.x));
                val.y = __uint_as_float(f2tf(val.y));
                val.z = __uint_as_float(f2tf(val.z));
                val.w = __uint_as_float(f2tf(val.w));
                *reinterpret_cast<float4*>(&Bs[k * 72 + c]) = val;
            }
        }
        __syncthreads();

#pragma unroll
        for (int ks = 0; ks < 4; ks++) {
            int kb = ks * 8;
            unsigned a[2][4];
            int ar = wr * 32 + (lane >> 2);
            int ak = kb + (lane & 3);
#pragma unroll
            for (int t = 0; t < 2; t++) {
                a[t][0] = __float_as_uint(As[(ar + t * 16) * 36 + ak]);
                a[t][1] = __float_as_uint(As[(ar + t * 16 + 8) * 36 + ak]);
                a[t][2] = __float_as_uint(As[(ar + t * 16) * 36 + ak + 4]);
                a[t][3] = __float_as_uint(As[(ar + t * 16 + 8) * 36 + ak + 4]);
            }
#pragma unroll
            for (int ct = 0; ct < 4; ct++) {
                int j = wc * 32 + ct * 8 + (lane >> 2);
                unsigned b0 = __float_as_uint(Bs[(kb + (lane & 3)) * 72 + j]);
                unsigned b1 = __float_as_uint(Bs[(kb + (lane & 3) + 4) * 72 + j]);
#pragma unroll
                for (int t = 0; t < 2; t++) {
                    asm volatile(
                        "mma.sync.aligned.m16n8k8.row.col.f32.tf32.tf32.f32 "
                        "{%0,%1,%2,%3}, {%4,%5,%6,%7}, {%8,%9}, {%0,%1,%2,%3};"
                        : "+f"(acc[t][ct][0]), "+f"(acc[t][ct][1]),
                          "+f"(acc[t][ct][2]), "+f"(acc[t][ct][3])
                        : "r"(a[t][0]), "r"(a[t][1]), "r"(a[t][2]), "r"(a[t][3]),
                          "r"(b0), "r"(b1));
                }
            }
        }
        __syncthreads();
    }

    float* xwv = g_xw + (size_t)blockIdx.y * MAXN * NHID;
#pragma unroll
    for (int t = 0; t < 2; t++) {
        int rb = row0 + wr * 32 + t * 16 + (lane >> 2);
#pragma unroll
        for (int ct = 0; ct < 4; ct++) {
            int col = wc * 32 + ct * 8 + (lane & 3) * 2;
            if (rb < N)
                *reinterpret_cast<float2*>(&xwv[(size_t)rb * NHID + col]) =
                    make_float2(acc[t][ct][0], acc[t][ct][1]);
            if (rb + 8 < N)
                *reinterpret_cast<float2*>(&xwv[(size_t)(rb + 8) * NHID + col]) =
                    make_float2(acc[t][ct][2], acc[t][ct][3]);
        }
    }
}

// ---------------- degree accumulation ----------------
__global__ void k_deg(const int* __restrict__ e0, const int* __restrict__ e1,
                      const int* __restrict__ e2,
                      const float* __restrict__ w0, const float* __restrict__ w1,
                      const float* __restrict__ w2, int E)
{
    int e = blockIdx.x * 256 + threadIdx.x;
    if (e >= E) return;
    int v = blockIdx.y;
    const int* ei = (v == 0) ? e0 : ((v == 1) ? e1 : e2);
    const float* ew = (v == 0) ? w0 : ((v == 1) ? w1 : w2);
    int dst = ei[E + e];
    atomicAdd(&g_deg[v * MAXN + dst], ew[e]);
    atomicAdd(&g_ecnt[v * MAXN + dst], 1);
}

// ---------------- 3-phase parallel exclusive scan (coalesced, full-chip) -------
__global__ __launch_bounds__(1024) void k_scanA(int N) {
    int v = blockIdx.y;
    int i = blockIdx.x * 1024 + threadIdx.x;
    int val = (i < N) ? g_ecnt[v * MAXN + i] : 0;
#pragma unroll
    for (int o = 16; o; o >>= 1) val += __shfl_xor_sync(0xffffffffu, val, o);
    __shared__ int ws[32];
    int lane = threadIdx.x & 31, wid = threadIdx.x >> 5;
    if (lane == 0) ws[wid] = val;
    __syncthreads();
    if (wid == 0) {
        int s = ws[lane];
#pragma unroll
        for (int o = 16; o; o >>= 1) s += __shfl_xor_sync(0xffffffffu, s, o);
        if (lane == 0) g_part[v * 64 + blockIdx.x] = s;
    }
}

__global__ void k_scanB(int nchunk, int N, int E) {
    int v = blockIdx.x;
    int t = threadIdx.x;                       // 64 threads
    int val = (t < nchunk) ? g_part[v * 64 + t] : 0;
    int inc = val;
    int lane = t & 31, wid = t >> 5;
#pragma unroll
    for (int o = 1; o < 32; o <<= 1) {
        int x = __shfl_up_sync(0xffffffffu, inc, o);
        if (lane >= o) inc += x;
    }
    __shared__ int tot;
    if (wid == 0 && lane == 31) tot = inc;
    __syncthreads();
    if (wid == 1) inc += tot;
    g_part[v * 64 + t] = inc - val;            // exclusive
    if (t == 0) g_rowstart[v * (MAXN + 1) + N] = E;
}

// scanC fused with normalizer computation + cursor init
__global__ __launch_bounds__(1024) void k_scanC(int N) {
    int v = blockIdx.y;
    int i = blockIdx.x * 1024 + threadIdx.x;
    int val = (i < N) ? g_ecnt[v * MAXN + i] : 0;
    int lane = threadIdx.x & 31, wid = threadIdx.x >> 5;
    int inc = val;
#pragma unroll
    for (int o = 1; o < 32; o <<= 1) {
        int x = __shfl_up_sync(0xffffffffu, inc, o);
        if (lane >= o) inc += x;
    }
    __shared__ int ws[32];
    if (lane == 31) ws[wid] = inc;
    __syncthreads();
    if (wid == 0) {
        int s = ws[lane];
        int sinc = s;
#pragma unroll
        for (int o = 1; o < 32; o <<= 1) {
            int x = __shfl_up_sync(0xffffffffu, sinc, o);
            if (lane >= o) sinc += x;
        }
        ws[lane] = sinc - s;
    }
    __syncthreads();
    int ex = inc - val + ws[wid] + g_part[v * 64 + blockIdx.x];
    if (i < N) {
        g_rowstart[v * (MAXN + 1) + i] = ex;
        g_wptr[v * MAXN + i] = ex;                        // absolute cursor
        float2 dv;
        dv.x = rsqrtf(g_deg[v * MAXN + i] + 1.0f);        // conv1: weighted deg + self loop
        dv.y = rsqrtf((float)(val + 1));                  // conv2: unit weights + self loop
        g_dinv[v * MAXN + i] = dv;
    }
}

// ---------------- CSR fill (counting-sort placement + packed edge record) ------
__global__ void k_fill(const int* __restrict__ e0, const int* __restrict__ e1,
                       const int* __restrict__ e2,
                       const float* __restrict__ w0, const float* __restrict__ w1,
                       const float* __restrict__ w2, int E)
{
    int e = blockIdx.x * 256 + threadIdx.x;
    if (e >= E) return;
    int v = blockIdx.y;
    const int* ei = (v == 0) ? e0 : ((v == 1) ? e1 : e2);
    const float* ew = (v == 0) ? w0 : ((v == 1) ? w1 : w2);
    int src = ei[e];
    int dst = ei[E + e];
    float w = ew[e];
    float ds = g_dinv[v * MAXN + src].x;
    float dd = g_dinv[v * MAXN + dst].x;
    int pos = atomicAdd(&g_wptr[v * MAXN + dst], 1);
    g_ed1[(size_t)v * MAXE + pos] = make_int2(src, __float_as_int(ds * w * dd));
}

// ---------------- conv1 aggregate + relu + feature sum + h@W2 (warp per node) --
// simple 4-way unrolled loop — ptxas front-batches the loads (known-good form)
__global__ __launch_bounds__(256) void k_agg(
    const float* __restrict__ b1a, const float* __restrict__ b1b, const float* __restrict__ b1c,
    const float* __restrict__ w2a, const float* __restrict__ w2b, const float* __restrict__ w2c,
    float* __restrict__ out, int N)
{
    int n = (blockIdx.x * 256 + threadIdx.x) >> 5;
    int lane = threadIdx.x & 31;
    if (n >= N) return;

    float2 f = make_float2(0.f, 0.f);
#pragma unroll
    for (int v = 0; v < 3; v++) {
        const float2* b1 = reinterpret_cast<const float2*>((v == 0) ? b1a : ((v == 1) ? b1b : b1c));
        const float2* w2 = reinterpret_cast<const float2*>((v == 0) ? w2a : ((v == 1) ? w2b : w2c));
        const float2* xw2 = reinterpret_cast<const float2*>(g_xw + (size_t)v * MAXN * NHID);
        float2 dvn = g_dinv[v * MAXN + n];
        float selfc = dvn.x * dvn.x;
        float2 a = xw2[(size_t)n * 32 + lane];
        a.x *= selfc; a.y *= selfc;

        int p  = g_rowstart[v * (MAXN + 1) + n];
        int pe = g_rowstart[v * (MAXN + 1) + n + 1];
        const int2* ed = g_ed1 + (size_t)v * MAXE;
        for (; p + 3 < pe; p += 4) {
            int2 e0 = ed[p],     e1 = ed[p + 1];
            int2 e2 = ed[p + 2], e3 = ed[p + 3];
            float2 x0 = xw2[(size_t)e0.x * 32 + lane];
            float2 x1 = xw2[(size_t)e1.x * 32 + lane];
            float2 x2 = xw2[(size_t)e2.x * 32 + lane];
            float2 x3 = xw2[(size_t)e3.x * 32 + lane];
            float c0 = __int_as_float(e0.y), c1 = __int_as_float(e1.y);
            float c2 = __int_as_float(e2.y), c3 = __int_as_float(e3.y);
            a.x = fmaf(x0.x, c0, a.x); a.y = fmaf(x0.y, c0, a.y);
            a.x = fmaf(x1.x, c1, a.x); a.y = fmaf(x1.y, c1, a.y);
            a.x = fmaf(x2.x, c2, a.x); a.y = fmaf(x2.y, c2, a.y);
            a.x = fmaf(x3.x, c3, a.x); a.y = fmaf(x3.y, c3, a.y);
        }
        for (; p < pe; p++) {
            int2 e0 = ed[p];
            float2 x0 = xw2[(size_t)e0.x * 32 + lane];
            float c0 = __int_as_float(e0.y);
            a.x = fmaf(x0.x, c0, a.x); a.y = fmaf(x0.y, c0, a.y);
        }

        float2 bb = b1[lane];
        float h0 = fmaxf(a.x + bb.x, 0.f);
        float h1 = fmaxf(a.y + bb.y, 0.f);
        f.x += h0; f.y += h1;
        float2 wv = w2[lane];
        float hw = h0 * wv.x + h1 * wv.y;
#pragma unroll
        for (int o = 16; o; o >>= 1) hw += __shfl_xor_sync(0xffffffffu, hw, o);
        if (lane == 0) g_hw2[v * MAXN + n] = make_float2(hw, dvn.y);
    }
    float2* fo = reinterpret_cast<float2*>(out + N + (size_t)n * NHID);
    fo[lane] = f;
}

// ---------------- conv2 aggregate -> x_flat (warp per node) ----------------
__global__ __launch_bounds__(256) void k_out(
    const float* __restrict__ b2a, const float* __restrict__ b2b, const float* __restrict__ b2c,
    float* __restrict__ out, int N)
{
    int n = (blockIdx.x * 256 + threadIdx.x) >> 5;
    int lane = threadIdx.x & 31;
    if (n >= N) return;
    float acc0 = 0.f, acc1 = 0.f, acc2 = 0.f;
    {
        int p0 = g_rowstart[0 * (MAXN + 1) + n];
        int p1 = g_rowstart[0 * (MAXN + 1) + n + 1];
        const int2* ed = g_ed1;
        for (int p = p0 + lane; p < p1; p += 32) {
            float2 hd = g_hw2[0 * MAXN + ed[p].x];
            acc0 += hd.x * hd.y;
        }
    }
    {
        int p0 = g_rowstart[1 * (MAXN + 1) + n];
        int p1 = g_rowstart[1 * (MAXN + 1) + n + 1];
        const int2* ed = g_ed1 + (size_t)MAXE;
        for (int p = p0 + lane; p < p1; p += 32) {
            float2 hd = g_hw2[1 * MAXN + ed[p].x];
            acc1 += hd.x * hd.y;
        }
    }
    {
        int p0 = g_rowstart[2 * (MAXN + 1) + n];
        int p1 = g_rowstart[2 * (MAXN + 1) + n + 1];
        const int2* ed = g_ed1 + (size_t)2 * MAXE;
        for (int p = p0 + lane; p < p1; p += 32) {
            float2 hd = g_hw2[2 * MAXN + ed[p].x];
            acc2 += hd.x * hd.y;
        }
    }
#pragma unroll
    for (int o = 16; o; o >>= 1) {
        acc0 += __shfl_xor_sync(0xffffffffu, acc0, o);
        acc1 += __shfl_xor_sync(0xffffffffu, acc1, o);
        acc2 += __shfl_xor_sync(0xffffffffu, acc2, o);
    }
    if (lane == 0) {
        float2 s0 = g_hw2[0 * MAXN + n];
        float2 s1 = g_hw2[1 * MAXN + n];
        float2 s2 = g_hw2[2 * MAXN + n];
        float t = s0.y * (acc0 + s0.y * s0.x) + b2a[0]
                + s1.y * (acc1 + s1.y * s1.x) + b2b[0]
                + s2.y * (acc2 + s2.y * s2.x) + b2c[0];
        out[n] = t;
    }
}

// ---------------- launch ----------------
extern "C" void kernel_launch(void* const* d_in, const int* in_sizes, int n_in,
                              void* d_out, int out_size)
{
    const float* x = (const float*)d_in[0];
    const int* ei0 = (const int*)d_in[1];
    const int* ei1 = (const int*)d_in[2];
    const int* ei2 = (const int*)d_in[3];
    const float* ew0 = (const float*)d_in[4];
    const float* ew1 = (const float*)d_in[5];
    const float* ew2 = (const float*)d_in[6];
    const float* W1a = (const float*)d_in[7];
    const float* b1a = (const float*)d_in[8];
    const float* W2a = (const float*)d_in[9];
    const float* b2a = (const float*)d_in[10];
    const float* W1b = (const float*)d_in[11];
    const float* b1b = (const float*)d_in[12];
    const float* W2b = (const float*)d_in[13];
    const float* b2b = (const float*)d_in[14];
    const float* W1c = (const float*)d_in[15];
    const float* b1c = (const float*)d_in[16];
    const float* W2c = (const float*)d_in[17];
    const float* b2c = (const float*)d_in[18];

    int N = in_sizes[0] / FIN;
    int E = in_sizes[1] / 2;
    float* out = (float*)d_out;

    int nb_n = (N + 255) / 256;
    int eb   = (E + 255) / 256;
    int nchunk = (N + 1023) / 1024;

    k_init<<<dim3(nb_n, 3), 256>>>(N);
    k_gemm<<<dim3((N + 127) / 128, 3), 256>>>(x, W1a, W1b, W1c, N);
    k_deg<<<dim3(eb, 3), 256>>>(ei0, ei1, ei2, ew0, ew1, ew2, E);
    k_scanA<<<dim3(nchunk, 3), 1024>>>(N);
    k_scanB<<<3, 64>>>(nchunk, N, E);
    k_scanC<<<dim3(nchunk, 3), 1024>>>(N);
    k_fill<<<dim3(eb, 3), 256>>>(ei0, ei1, ei2, ew0, ew1, ew2, E);
    k_agg<<<(N + 7) / 8, 256>>>(b1a, b1b, b1c, W2a, W2b, W2c, out, N);
    k_out<<<(N + 7) / 8, 256>>>(b2a, b2b, b2c, out, N);
}

// round 16
// speedup vs baseline: 1.3812x; 1.0606x over previous
#include <cuda_runtime.h>
#include <cstdint>
#include <cstddef>

#define FIN   256
#define NHID  64
#define MAXN  50176
#define MAXE  800064

// ---------------- scratch (static device memory; no allocations) ----------------
__device__ float  g_xw[(size_t)3 * MAXN * NHID];  // x @ W1 per view  [v][n][64]
__device__ float  g_deg[3 * MAXN];                // weighted in-degree (no self loop; +1 at norm)
__device__ float2 g_dinv[3 * MAXN];               // (rsqrt(deg+1), rsqrt(count+1))
__device__ float2 g_hw2[3 * MAXN];                // (h @ W2, dinv2) per node per view
__device__ int    g_ecnt[3 * MAXN];               // in-edge counts
__device__ int    g_wptr[3 * MAXN];               // CSR fill cursors (absolute)
__device__ int    g_rowstart[3 * (MAXN + 1)];     // CSR row offsets
__device__ int    g_part[3 * 64];                 // scan partials
__device__ int2   g_ed1[(size_t)3 * MAXE];        // packed (src, dinv1[src]*w bits) per CSR slot

// ---------------- init: zero counters ----------------
__global__ void k_init(int N) {
    int n = blockIdx.x * 256 + threadIdx.x;
    int v = blockIdx.y;
    if (n < N) {
        g_deg[v * MAXN + n]  = 0.0f;
        g_ecnt[v * MAXN + n] = 0;
    }
}

// ---------------- GEMM: xw[v] = X[N,256] @ W1_v[256,64] (tf32 mma.sync) --------
__device__ __forceinline__ unsigned f2tf(float f) {
    unsigned r;
    asm("cvt.rna.tf32.f32 %0, %1;" : "=r"(r) : "f"(f));
    return r;
}

__global__ __launch_bounds__(256) void k_gemm(
    const float* __restrict__ X,
    const float* __restrict__ Wa, const float* __restrict__ Wb, const float* __restrict__ Wc,
    int N)
{
    __shared__ __align__(16) float As[128 * 36];  // 128 rows x 32 k (pad 36)
    __shared__ __align__(16) float Bs[32 * 72];   // 32 k x 64 cols (pad 72)

    const float* W = (blockIdx.y == 0) ? Wa : ((blockIdx.y == 1) ? Wb : Wc);
    int row0 = blockIdx.x * 128;
    int tid  = threadIdx.x;
    int lane = tid & 31, warp = tid >> 5;
    int wr = warp >> 1;   // 0..3 : 32-row group
    int wc = warp & 1;    // 0..1 : 32-col group

    float acc[2][4][4];
#pragma unroll
    for (int a = 0; a < 2; a++)
#pragma unroll
        for (int b = 0; b < 4; b++)
#pragma unroll
            for (int c = 0; c < 4; c++) acc[a][b][c] = 0.f;

    for (int kc = 0; kc < FIN; kc += 32) {
        {
            int c = (tid & 7) * 4;
#pragma unroll
            for (int it = 0; it < 4; it++) {
                int r = (tid >> 3) + it * 32;
                int gr = row0 + r;
                float4 val = make_float4(0.f, 0.f, 0.f, 0.f);
                if (gr < N) val = *reinterpret_cast<const float4*>(X + (size_t)gr * FIN + kc + c);
                val.x = __uint_as_float(f2tf(val.x));
                val.y = __uint_as_float(f2tf(val.y));
                val.z = __uint_as_float(f2tf(val.z));
                val.w = __uint_as_float(f2tf(val.w));
                *reinterpret_cast<float4*>(&As[r * 36 + c]) = val;
            }
        }
        {
            int c = (tid & 15) * 4;
#pragma unroll
            for (int it = 0; it < 2; it++) {
                int k = (tid >> 4) + it * 16;
                float4 val = *reinterpret_cast<const float4*>(W + (size_t)(kc + k) * NHID + c);
                val.x = __uint_as_float(f2tf(val.x));
                val.y = __uint_as_float(f2tf(val.y));
                val.z = __uint_as_float(f2tf(val.z));
                val.w = __uint_as_float(f2tf(val.w));
                *reinterpret_cast<float4*>(&Bs[k * 72 + c]) = val;
            }
        }
        __syncthreads();

#pragma unroll
        for (int ks = 0; ks < 4; ks++) {
            int kb = ks * 8;
            unsigned a[2][4];
            int ar = wr * 32 + (lane >> 2);
            int ak = kb + (lane & 3);
#pragma unroll
            for (int t = 0; t < 2; t++) {
                a[t][0] = __float_as_uint(As[(ar + t * 16) * 36 + ak]);
                a[t][1] = __float_as_uint(As[(ar + t * 16 + 8) * 36 + ak]);
                a[t][2] = __float_as_uint(As[(ar + t * 16) * 36 + ak + 4]);
                a[t][3] = __float_as_uint(As[(ar + t * 16 + 8) * 36 + ak + 4]);
            }
#pragma unroll
            for (int ct = 0; ct < 4; ct++) {
                int j = wc * 32 + ct * 8 + (lane >> 2);
                unsigned b0 = __float_as_uint(Bs[(kb + (lane & 3)) * 72 + j]);
                unsigned b1 = __float_as_uint(Bs[(kb + (lane & 3) + 4) * 72 + j]);
#pragma unroll
                for (int t = 0; t < 2; t++) {
                    asm volatile(
                        "mma.sync.aligned.m16n8k8.row.col.f32.tf32.tf32.f32 "
                        "{%0,%1,%2,%3}, {%4,%5,%6,%7}, {%8,%9}, {%0,%1,%2,%3};"
                        : "+f"(acc[t][ct][0]), "+f"(acc[t][ct][1]),
                          "+f"(acc[t][ct][2]), "+f"(acc[t][ct][3])
                        : "r"(a[t][0]), "r"(a[t][1]), "r"(a[t][2]), "r"(a[t][3]),
                          "r"(b0), "r"(b1));
                }
            }
        }
        __syncthreads();
    }

    float* xwv = g_xw + (size_t)blockIdx.y * MAXN * NHID;
#pragma unroll
    for (int t = 0; t < 2; t++) {
        int rb = row0 + wr * 32 + t * 16 + (lane >> 2);
#pragma unroll
        for (int ct = 0; ct < 4; ct++) {
            int col = wc * 32 + ct * 8 + (lane & 3) * 2;
            if (rb < N)
                *reinterpret_cast<float2*>(&xwv[(size_t)rb * NHID + col]) =
                    make_float2(acc[t][ct][0], acc[t][ct][1]);
            if (rb + 8 < N)
                *reinterpret_cast<float2*>(&xwv[(size_t)(rb + 8) * NHID + col]) =
                    make_float2(acc[t][ct][2], acc[t][ct][3]);
        }
    }
}

// ---------------- degree accumulation ----------------
__global__ void k_deg(const int* __restrict__ e0, const int* __restrict__ e1,
                      const int* __restrict__ e2,
                      const float* __restrict__ w0, const float* __restrict__ w1,
                      const float* __restrict__ w2, int E)
{
    int e = blockIdx.x * 256 + threadIdx.x;
    if (e >= E) return;
    int v = blockIdx.y;
    const int* ei = (v == 0) ? e0 : ((v == 1) ? e1 : e2);
    const float* ew = (v == 0) ? w0 : ((v == 1) ? w1 : w2);
    int dst = ei[E + e];
    atomicAdd(&g_deg[v * MAXN + dst], ew[e]);
    atomicAdd(&g_ecnt[v * MAXN + dst], 1);
}

// ---------------- 3-phase parallel exclusive scan (coalesced, full-chip) -------
__global__ __launch_bounds__(1024) void k_scanA(int N) {
    int v = blockIdx.y;
    int i = blockIdx.x * 1024 + threadIdx.x;
    int val = (i < N) ? g_ecnt[v * MAXN + i] : 0;
#pragma unroll
    for (int o = 16; o; o >>= 1) val += __shfl_xor_sync(0xffffffffu, val, o);
    __shared__ int ws[32];
    int lane = threadIdx.x & 31, wid = threadIdx.x >> 5;
    if (lane == 0) ws[wid] = val;
    __syncthreads();
    if (wid == 0) {
        int s = ws[lane];
#pragma unroll
        for (int o = 16; o; o >>= 1) s += __shfl_xor_sync(0xffffffffu, s, o);
        if (lane == 0) g_part[v * 64 + blockIdx.x] = s;
    }
}

__global__ void k_scanB(int nchunk, int N, int E) {
    int v = blockIdx.x;
    int t = threadIdx.x;                       // 64 threads
    int val = (t < nchunk) ? g_part[v * 64 + t] : 0;
    int inc = val;
    int lane = t & 31, wid = t >> 5;
#pragma unroll
    for (int o = 1; o < 32; o <<= 1) {
        int x = __shfl_up_sync(0xffffffffu, inc, o);
        if (lane >= o) inc += x;
    }
    __shared__ int tot;
    if (wid == 0 && lane == 31) tot = inc;
    __syncthreads();
    if (wid == 1) inc += tot;
    g_part[v * 64 + t] = inc - val;            // exclusive
    if (t == 0) g_rowstart[v * (MAXN + 1) + N] = E;
}

// scanC fused with normalizer computation + cursor init
__global__ __launch_bounds__(1024) void k_scanC(int N) {
    int v = blockIdx.y;
    int i = blockIdx.x * 1024 + threadIdx.x;
    int val = (i < N) ? g_ecnt[v * MAXN + i] : 0;
    int lane = threadIdx.x & 31, wid = threadIdx.x >> 5;
    int inc = val;
#pragma unroll
    for (int o = 1; o < 32; o <<= 1) {
        int x = __shfl_up_sync(0xffffffffu, inc, o);
        if (lane >= o) inc += x;
    }
    __shared__ int ws[32];
    if (lane == 31) ws[wid] = inc;
    __syncthreads();
    if (wid == 0) {
        int s = ws[lane];
        int sinc = s;
#pragma unroll
        for (int o = 1; o < 32; o <<= 1) {
            int x = __shfl_up_sync(0xffffffffu, sinc, o);
            if (lane >= o) sinc += x;
        }
        ws[lane] = sinc - s;
    }
    __syncthreads();
    int ex = inc - val + ws[wid] + g_part[v * 64 + blockIdx.x];
    if (i < N) {
        g_rowstart[v * (MAXN + 1) + i] = ex;
        g_wptr[v * MAXN + i] = ex;                        // absolute cursor
        float2 dv;
        dv.x = rsqrtf(g_deg[v * MAXN + i] + 1.0f);        // conv1: weighted deg + self loop
        dv.y = rsqrtf((float)(val + 1));                  // conv2: unit weights + self loop
        g_dinv[v * MAXN + i] = dv;
    }
}

// ---------------- CSR fill: record = (src, dinv1[src]*w); dst factor applied in agg
__global__ void k_fill(const int* __restrict__ e0, const int* __restrict__ e1,
                       const int* __restrict__ e2,
                       const float* __restrict__ w0, const float* __restrict__ w1,
                       const float* __restrict__ w2, int E)
{
    int e = blockIdx.x * 256 + threadIdx.x;
    if (e >= E) return;
    int v = blockIdx.y;
    const int* ei = (v == 0) ? e0 : ((v == 1) ? e1 : e2);
    const float* ew = (v == 0) ? w0 : ((v == 1) ? w1 : w2);
    int src = ei[e];
    int dst = ei[E + e];
    float w = ew[e];
    float ds = g_dinv[v * MAXN + src].x;
    int pos = atomicAdd(&g_wptr[v * MAXN + dst], 1);
    g_ed1[(size_t)v * MAXE + pos] = make_int2(src, __float_as_int(ds * w));
}

// ---------------- conv1 aggregate + relu + feature sum + h@W2 (warp per node) --
// straight 8-way unrolled loop — ptxas front-batches 16 loads per iteration
__global__ __launch_bounds__(256) void k_agg(
    const float* __restrict__ b1a, const float* __restrict__ b1b, const float* __restrict__ b1c,
    const float* __restrict__ w2a, const float* __restrict__ w2b, const float* __restrict__ w2c,
    float* __restrict__ out, int N)
{
    int n = (blockIdx.x * 256 + threadIdx.x) >> 5;
    int lane = threadIdx.x & 31;
    if (n >= N) return;

    float2 f = make_float2(0.f, 0.f);
#pragma unroll
    for (int v = 0; v < 3; v++) {
        const float2* b1 = reinterpret_cast<const float2*>((v == 0) ? b1a : ((v == 1) ? b1b : b1c));
        const float2* w2 = reinterpret_cast<const float2*>((v == 0) ? w2a : ((v == 1) ? w2b : w2c));
        const float2* xw2 = reinterpret_cast<const float2*>(g_xw + (size_t)v * MAXN * NHID);
        float2 dvn = g_dinv[v * MAXN + n];
        float2 a = xw2[(size_t)n * 32 + lane];
        a.x *= dvn.x; a.y *= dvn.x;              // self term: dinv1[n]*xw; row scale applied after

        int p  = g_rowstart[v * (MAXN + 1) + n];
        int pe = g_rowstart[v * (MAXN + 1) + n + 1];
        const int2* ed = g_ed1 + (size_t)v * MAXE;
        for (; p + 7 < pe; p += 8) {
            int2 e0 = ed[p],     e1 = ed[p + 1], e2 = ed[p + 2], e3 = ed[p + 3];
            int2 e4 = ed[p + 4], e5 = ed[p + 5], e6 = ed[p + 6], e7 = ed[p + 7];
            float2 x0 = xw2[(size_t)e0.x * 32 + lane];
            float2 x1 = xw2[(size_t)e1.x * 32 + lane];
            float2 x2 = xw2[(size_t)e2.x * 32 + lane];
            float2 x3 = xw2[(size_t)e3.x * 32 + lane];
            float2 x4 = xw2[(size_t)e4.x * 32 + lane];
            float2 x5 = xw2[(size_t)e5.x * 32 + lane];
            float2 x6 = xw2[(size_t)e6.x * 32 + lane];
            float2 x7 = xw2[(size_t)e7.x * 32 + lane];
            float c0 = __int_as_float(e0.y), c1 = __int_as_float(e1.y);
            float c2 = __int_as_float(e2.y), c3 = __int_as_float(e3.y);
            float c4 = __int_as_float(e4.y), c5 = __int_as_float(e5.y);
            float c6 = __int_as_float(e6.y), c7 = __int_as_float(e7.y);
            a.x = fmaf(x0.x, c0, a.x); a.y = fmaf(x0.y, c0, a.y);
            a.x = fmaf(x1.x, c1, a.x); a.y = fmaf(x1.y, c1, a.y);
            a.x = fmaf(x2.x, c2, a.x); a.y = fmaf(x2.y, c2, a.y);
            a.x = fmaf(x3.x, c3, a.x); a.y = fmaf(x3.y, c3, a.y);
            a.x = fmaf(x4.x, c4, a.x); a.y = fmaf(x4.y, c4, a.y);
            a.x = fmaf(x5.x, c5, a.x); a.y = fmaf(x5.y, c5, a.y);
            a.x = fmaf(x6.x, c6, a.x); a.y = fmaf(x6.y, c6, a.y);
            a.x = fmaf(x7.x, c7, a.x); a.y = fmaf(x7.y, c7, a.y);
        }
        for (; p + 1 < pe; p += 2) {
            int2 e0 = ed[p], e1 = ed[p + 1];
            float2 x0 = xw2[(size_t)e0.x * 32 + lane];
            float2 x1 = xw2[(size_t)e1.x * 32 + lane];
            float c0 = __int_as_float(e0.y), c1 = __int_as_float(e1.y);
            a.x = fmaf(x0.x, c0, a.x); a.y = fmaf(x0.y, c0, a.y);
            a.x = fmaf(x1.x, c1, a.x); a.y = fmaf(x1.y, c1, a.y);
        }
        if (p < pe) {
            int2 e0 = ed[p];
            float2 x0 = xw2[(size_t)e0.x * 32 + lane];
            float c0 = __int_as_float(e0.y);
            a.x = fmaf(x0.x, c0, a.x); a.y = fmaf(x0.y, c0, a.y);
        }
        a.x *= dvn.x; a.y *= dvn.x;              // apply dinv1[dst] to whole row sum

        float2 bb = b1[lane];
        float h0 = fmaxf(a.x + bb.x, 0.f);
        float h1 = fmaxf(a.y + bb.y, 0.f);
        f.x += h0; f.y += h1;
        float2 wv = w2[lane];
        float hw = h0 * wv.x + h1 * wv.y;
#pragma unroll
        for (int o = 16; o; o >>= 1) hw += __shfl_xor_sync(0xffffffffu, hw, o);
        if (lane == 0) g_hw2[v * MAXN + n] = make_float2(hw, dvn.y);
    }
    float2* fo = reinterpret_cast<float2*>(out + N + (size_t)n * NHID);
    fo[lane] = f;
}

// ---------------- conv2 aggregate -> x_flat (warp per node) ----------------
__global__ __launch_bounds__(256) void k_out(
    const float* __restrict__ b2a, const float* __restrict__ b2b, const float* __restrict__ b2c,
    float* __restrict__ out, int N)
{
    int n = (blockIdx.x * 256 + threadIdx.x) >> 5;
    int lane = threadIdx.x & 31;
    if (n >= N) return;
    float acc0 = 0.f, acc1 = 0.f, acc2 = 0.f;
    {
        int p0 = g_rowstart[0 * (MAXN + 1) + n];
        int p1 = g_rowstart[0 * (MAXN + 1) + n + 1];
        const int2* ed = g_ed1;
        for (int p = p0 + lane; p < p1; p += 32) {
            float2 hd = g_hw2[0 * MAXN + ed[p].x];
            acc0 += hd.x * hd.y;
        }
    }
    {
        int p0 = g_rowstart[1 * (MAXN + 1) + n];
        int p1 = g_rowstart[1 * (MAXN + 1) + n + 1];
        const int2* ed = g_ed1 + (size_t)MAXE;
        for (int p = p0 + lane; p < p1; p += 32) {
            float2 hd = g_hw2[1 * MAXN + ed[p].x];
            acc1 += hd.x * hd.y;
        }
    }
    {
        int p0 = g_rowstart[2 * (MAXN + 1) + n];
        int p1 = g_rowstart[2 * (MAXN + 1) + n + 1];
        const int2* ed = g_ed1 + (size_t)2 * MAXE;
        for (int p = p0 + lane; p < p1; p += 32) {
            float2 hd = g_hw2[2 * MAXN + ed[p].x];
            acc2 += hd.x * hd.y;
        }
    }
#pragma unroll
    for (int o = 16; o; o >>= 1) {
        acc0 += __shfl_xor_sync(0xffffffffu, acc0, o);
        acc1 += __shfl_xor_sync(0xffffffffu, acc1, o);
        acc2 += __shfl_xor_sync(0xffffffffu, acc2, o);
    }
    if (lane == 0) {
        float2 s0 = g_hw2[0 * MAXN + n];
        float2 s1 = g_hw2[1 * MAXN + n];
        float2 s2 = g_hw2[2 * MAXN + n];
        float t = s0.y * (acc0 + s0.y * s0.x) + b2a[0]
                + s1.y * (acc1 + s1.y * s1.x) + b2b[0]
                + s2.y * (acc2 + s2.y * s2.x) + b2c[0];
        out[n] = t;
    }
}

// ---------------- launch ----------------
extern "C" void kernel_launch(void* const* d_in, const int* in_sizes, int n_in,
                              void* d_out, int out_size)
{
    const float* x = (const float*)d_in[0];
    const int* ei0 = (const int*)d_in[1];
    const int* ei1 = (const int*)d_in[2];
    const int* ei2 = (const int*)d_in[3];
    const float* ew0 = (const float*)d_in[4];
    const float* ew1 = (const float*)d_in[5];
    const float* ew2 = (const float*)d_in[6];
    const float* W1a = (const float*)d_in[7];
    const float* b1a = (const float*)d_in[8];
    const float* W2a = (const float*)d_in[9];
    const float* b2a = (const float*)d_in[10];
    const float* W1b = (const float*)d_in[11];
    const float* b1b = (const float*)d_in[12];
    const float* W2b = (const float*)d_in[13];
    const float* b2b = (const float*)d_in[14];
    const float* W1c = (const float*)d_in[15];
    const float* b1c = (const float*)d_in[16];
    const float* W2c = (const float*)d_in[17];
    const float* b2c = (const float*)d_in[18];

    int N = in_sizes[0] / FIN;
    int E = in_sizes[1] / 2;
    float* out = (float*)d_out;

    int nb_n = (N + 255) / 256;
    int eb   = (E + 255) / 256;
    int nchunk = (N + 1023) / 1024;

    k_init<<<dim3(nb_n, 3), 256>>>(N);
    k_gemm<<<dim3((N + 127) / 128, 3), 256>>>(x, W1a, W1b, W1c, N);
    k_deg<<<dim3(eb, 3), 256>>>(ei0, ei1, ei2, ew0, ew1, ew2, E);
    k_scanA<<<dim3(nchunk, 3), 1024>>>(N);
    k_scanB<<<3, 64>>>(nchunk, N, E);
    k_scanC<<<dim3(nchunk, 3), 1024>>>(N);
    k_fill<<<dim3(eb, 3), 256>>>(ei0, ei1, ei2, ew0, ew1, ew2, E);
    k_agg<<<(N + 7) / 8, 256>>>(b1a, b1b, b1c, W2a, W2b, W2c, out, N);
    k_out<<<(N + 7) / 8, 256>>>(b2a, b2b, b2c, out, N);
}

// round 17
// speedup vs baseline: 1.4519x; 1.0512x over previous
#include <cuda_runtime.h>
#include <cuda_fp16.h>
#include <cstdint>
#include <cstddef>

#define FIN   256
#define NHID  64
#define MAXN  50176
#define MAXE  800064

// ---------------- scratch (static device memory; no allocations) ----------------
__device__ __half2 g_xwh[(size_t)3 * MAXN * 32]; // dinv1-prescaled x@W1 in fp16  [v][n][32 half2]
__device__ float  g_deg[3 * MAXN];                // weighted in-degree (no self loop; +1 at norm)
__device__ float2 g_dinv[3 * MAXN];               // (rsqrt(deg+1), rsqrt(count+1))
__device__ float2 g_hw2[3 * MAXN];                // (h @ W2, dinv2) per node per view
__device__ int    g_ecnt[3 * MAXN];               // in-edge counts
__device__ int    g_wptr[3 * MAXN];               // CSR fill cursors (absolute)
__device__ int    g_rowstart[3 * (MAXN + 1)];     // CSR row offsets
__device__ int    g_part[3 * 64];                 // scan partials
__device__ int2   g_ed1[(size_t)3 * MAXE];        // packed (src, w bits) per CSR slot

// ---------------- init: zero counters ----------------
__global__ void k_init(int N) {
    int n = blockIdx.x * 256 + threadIdx.x;
    int v = blockIdx.y;
    if (n < N) {
        g_deg[v * MAXN + n]  = 0.0f;
        g_ecnt[v * MAXN + n] = 0;
    }
}

// ---------------- degree accumulation ----------------
__global__ void k_deg(const int* __restrict__ e0, const int* __restrict__ e1,
                      const int* __restrict__ e2,
                      const float* __restrict__ w0, const float* __restrict__ w1,
                      const float* __restrict__ w2, int E)
{
    int e = blockIdx.x * 256 + threadIdx.x;
    if (e >= E) return;
    int v = blockIdx.y;
    const int* ei = (v == 0) ? e0 : ((v == 1) ? e1 : e2);
    const float* ew = (v == 0) ? w0 : ((v == 1) ? w1 : w2);
    int dst = ei[E + e];
    atomicAdd(&g_deg[v * MAXN + dst], ew[e]);
    atomicAdd(&g_ecnt[v * MAXN + dst], 1);
}

// ---------------- 3-phase parallel exclusive scan (coalesced, full-chip) -------
__global__ __launch_bounds__(1024) void k_scanA(int N) {
    int v = blockIdx.y;
    int i = blockIdx.x * 1024 + threadIdx.x;
    int val = (i < N) ? g_ecnt[v * MAXN + i] : 0;
#pragma unroll
    for (int o = 16; o; o >>= 1) val += __shfl_xor_sync(0xffffffffu, val, o);
    __shared__ int ws[32];
    int lane = threadIdx.x & 31, wid = threadIdx.x >> 5;
    if (lane == 0) ws[wid] = val;
    __syncthreads();
    if (wid == 0) {
        int s = ws[lane];
#pragma unroll
        for (int o = 16; o; o >>= 1) s += __shfl_xor_sync(0xffffffffu, s, o);
        if (lane == 0) g_part[v * 64 + blockIdx.x] = s;
    }
}

__global__ void k_scanB(int nchunk, int N, int E) {
    int v = blockIdx.x;
    int t = threadIdx.x;                       // 64 threads
    int val = (t < nchunk) ? g_part[v * 64 + t] : 0;
    int inc = val;
    int lane = t & 31, wid = t >> 5;
#pragma unroll
    for (int o = 1; o < 32; o <<= 1) {
        int x = __shfl_up_sync(0xffffffffu, inc, o);
        if (lane >= o) inc += x;
    }
    __shared__ int tot;
    if (wid == 0 && lane == 31) tot = inc;
    __syncthreads();
    if (wid == 1) inc += tot;
    g_part[v * 64 + t] = inc - val;            // exclusive
    if (t == 0) g_rowstart[v * (MAXN + 1) + N] = E;
}

// scanC fused with normalizer computation + cursor init
__global__ __launch_bounds__(1024) void k_scanC(int N) {
    int v = blockIdx.y;
    int i = blockIdx.x * 1024 + threadIdx.x;
    int val = (i < N) ? g_ecnt[v * MAXN + i] : 0;
    int lane = threadIdx.x & 31, wid = threadIdx.x >> 5;
    int inc = val;
#pragma unroll
    for (int o = 1; o < 32; o <<= 1) {
        int x = __shfl_up_sync(0xffffffffu, inc, o);
        if (lane >= o) inc += x;
    }
    __shared__ int ws[32];
    if (lane == 31) ws[wid] = inc;
    __syncthreads();
    if (wid == 0) {
        int s = ws[lane];
        int sinc = s;
#pragma unroll
        for (int o = 1; o < 32; o <<= 1) {
            int x = __shfl_up_sync(0xffffffffu, sinc, o);
            if (lane >= o) sinc += x;
        }
        ws[lane] = sinc - s;
    }
    __syncthreads();
    int ex = inc - val + ws[wid] + g_part[v * 64 + blockIdx.x];
    if (i < N) {
        g_rowstart[v * (MAXN + 1) + i] = ex;
        g_wptr[v * MAXN + i] = ex;                        // absolute cursor
        float2 dv;
        dv.x = rsqrtf(g_deg[v * MAXN + i] + 1.0f);        // conv1: weighted deg + self loop
        dv.y = rsqrtf((float)(val + 1));                  // conv2: unit weights + self loop
        g_dinv[v * MAXN + i] = dv;
    }
}

// ---------------- GEMM: xw'[v] = dinv1 * (X @ W1_v), stored fp16 --------------
__device__ __forceinline__ unsigned f2tf(float f) {
    unsigned r;
    asm("cvt.rna.tf32.f32 %0, %1;" : "=r"(r) : "f"(f));
    return r;
}

__global__ __launch_bounds__(256) void k_gemm(
    const float* __restrict__ X,
    const float* __restrict__ Wa, const float* __restrict__ Wb, const float* __restrict__ Wc,
    int N)
{
    __shared__ __align__(16) float As[128 * 36];  // 128 rows x 32 k (pad 36)
    __shared__ __align__(16) float Bs[32 * 72];   // 32 k x 64 cols (pad 72)

    const float* W = (blockIdx.y == 0) ? Wa : ((blockIdx.y == 1) ? Wb : Wc);
    int row0 = blockIdx.x * 128;
    int tid  = threadIdx.x;
    int lane = tid & 31, warp = tid >> 5;
    int wr = warp >> 1;   // 0..3 : 32-row group
    int wc = warp & 1;    // 0..1 : 32-col group

    float acc[2][4][4];
#pragma unroll
    for (int a = 0; a < 2; a++)
#pragma unroll
        for (int b = 0; b < 4; b++)
#pragma unroll
            for (int c = 0; c < 4; c++) acc[a][b][c] = 0.f;

    for (int kc = 0; kc < FIN; kc += 32) {
        {
            int c = (tid & 7) * 4;
#pragma unroll
            for (int it = 0; it < 4; it++) {
                int r = (tid >> 3) + it * 32;
                int gr = row0 + r;
                float4 val = make_float4(0.f, 0.f, 0.f, 0.f);
                if (gr < N) val = *reinterpret_cast<const float4*>(X + (size_t)gr * FIN + kc + c);
                val.x = __uint_as_float(f2tf(val.x));
                val.y = __uint_as_float(f2tf(val.y));
                val.z = __uint_as_float(f2tf(val.z));
                val.w = __uint_as_float(f2tf(val.w));
                *reinterpret_cast<float4*>(&As[r * 36 + c]) = val;
            }
        }
        {
            int c = (tid & 15) * 4;
#pragma unroll
            for (int it = 0; it < 2; it++) {
                int k = (tid >> 4) + it * 16;
                float4 val = *reinterpret_cast<const float4*>(W + (size_t)(kc + k) * NHID + c);
                val.x = __uint_as_float(f2tf(val.x));
                val.y = __uint_as_float(f2tf(val.y));
                val.z = __uint_as_float(f2tf(val.z));
                val.w = __uint_as_float(f2tf(val.w));
                *reinterpret_cast<float4*>(&Bs[k * 72 + c]) = val;
            }
        }
        __syncthreads();

#pragma unroll
        for (int ks = 0; ks < 4; ks++) {
            int kb = ks * 8;
            unsigned a[2][4];
            int ar = wr * 32 + (lane >> 2);
            int ak = kb + (lane & 3);
#pragma unroll
            for (int t = 0; t < 2; t++) {
                a[t][0] = __float_as_uint(As[(ar + t * 16) * 36 + ak]);
                a[t][1] = __float_as_uint(As[(ar + t * 16 + 8) * 36 + ak]);
                a[t][2] = __float_as_uint(As[(ar + t * 16) * 36 + ak + 4]);
                a[t][3] = __float_as_uint(As[(ar + t * 16 + 8) * 36 + ak + 4]);
            }
#pragma unroll
            for (int ct = 0; ct < 4; ct++) {
                int j = wc * 32 + ct * 8 + (lane >> 2);
                unsigned b0 = __float_as_uint(Bs[(kb + (lane & 3)) * 72 + j]);
                unsigned b1 = __float_as_uint(Bs[(kb + (lane & 3) + 4) * 72 + j]);
#pragma unroll
                for (int t = 0; t < 2; t++) {
                    asm volatile(
                        "mma.sync.aligned.m16n8k8.row.col.f32.tf32.tf32.f32 "
                        "{%0,%1,%2,%3}, {%4,%5,%6,%7}, {%8,%9}, {%0,%1,%2,%3};"
                        : "+f"(acc[t][ct][0]), "+f"(acc[t][ct][1]),
                          "+f"(acc[t][ct][2]), "+f"(acc[t][ct][3])
                        : "r"(a[t][0]), "r"(a[t][1]), "r"(a[t][2]), "r"(a[t][3]),
                          "r"(b0), "r"(b1));
                }
            }
        }
        __syncthreads();
    }

    // epilogue: scale row by dinv1[row], convert to fp16, store
    int v = blockIdx.y;
    __half2* xwv = g_xwh + (size_t)v * MAXN * 32;
#pragma unroll
    for (int t = 0; t < 2; t++) {
        int rb = row0 + wr * 32 + t * 16 + (lane >> 2);
        float s0 = (rb < N)     ? g_dinv[v * MAXN + rb].x     : 0.f;
        float s1 = (rb + 8 < N) ? g_dinv[v * MAXN + rb + 8].x : 0.f;
#pragma unroll
        for (int ct = 0; ct < 4; ct++) {
            int col2 = wc * 16 + ct * 4 + (lane & 3);   // half2 column index
            if (rb < N)
                xwv[(size_t)rb * 32 + col2] =
                    __floats2half2_rn(acc[t][ct][0] * s0, acc[t][ct][1] * s0);
            if (rb + 8 < N)
                xwv[(size_t)(rb + 8) * 32 + col2] =
                    __floats2half2_rn(acc[t][ct][2] * s1, acc[t][ct][3] * s1);
        }
    }
}

// ---------------- CSR fill: record = (src, w) — no gathers at all --------------
__global__ void k_fill(const int* __restrict__ e0, const int* __restrict__ e1,
                       const int* __restrict__ e2,
                       const float* __restrict__ w0, const float* __restrict__ w1,
                       const float* __restrict__ w2, int E)
{
    int e = blockIdx.x * 256 + threadIdx.x;
    if (e >= E) return;
    int v = blockIdx.y;
    const int* ei = (v == 0) ? e0 : ((v == 1) ? e1 : e2);
    const float* ew = (v == 0) ? w0 : ((v == 1) ? w1 : w2);
    int src = ei[e];
    int dst = ei[E + e];
    float w = ew[e];
    int pos = atomicAdd(&g_wptr[v * MAXN + dst], 1);
    g_ed1[(size_t)v * MAXE + pos] = make_int2(src, __float_as_int(w));
}

// ---------------- conv1 aggregate + relu + feature sum + h@W2 (warp per node) --
// straight 8-way unrolled loop; fp16 row gathers = 1 L2 line per row
__global__ __launch_bounds__(256) void k_agg(
    const float* __restrict__ b1a, const float* __restrict__ b1b, const float* __restrict__ b1c,
    const float* __restrict__ w2a, const float* __restrict__ w2b, const float* __restrict__ w2c,
    float* __restrict__ out, int N)
{
    int n = (blockIdx.x * 256 + threadIdx.x) >> 5;
    int lane = threadIdx.x & 31;
    if (n >= N) return;

    float2 f = make_float2(0.f, 0.f);
#pragma unroll
    for (int v = 0; v < 3; v++) {
        const float2* b1 = reinterpret_cast<const float2*>((v == 0) ? b1a : ((v == 1) ? b1b : b1c));
        const float2* w2 = reinterpret_cast<const float2*>((v == 0) ? w2a : ((v == 1) ? w2b : w2c));
        const __half2* xh = g_xwh + (size_t)v * MAXN * 32;
        float2 dvn = g_dinv[v * MAXN + n];
        float2 a = __half22float2(xh[(size_t)n * 32 + lane]);   // self term xw'[n]

        int p  = g_rowstart[v * (MAXN + 1) + n];
        int pe = g_rowstart[v * (MAXN + 1) + n + 1];
        const int2* ed = g_ed1 + (size_t)v * MAXE;
        for (; p + 7 < pe; p += 8) {
            int2 e0 = ed[p],     e1 = ed[p + 1], e2 = ed[p + 2], e3 = ed[p + 3];
            int2 e4 = ed[p + 4], e5 = ed[p + 5], e6 = ed[p + 6], e7 = ed[p + 7];
            __half2 r0 = xh[(size_t)e0.x * 32 + lane];
            __half2 r1 = xh[(size_t)e1.x * 32 + lane];
            __half2 r2 = xh[(size_t)e2.x * 32 + lane];
            __half2 r3 = xh[(size_t)e3.x * 32 + lane];
            __half2 r4 = xh[(size_t)e4.x * 32 + lane];
            __half2 r5 = xh[(size_t)e5.x * 32 + lane];
            __half2 r6 = xh[(size_t)e6.x * 32 + lane];
            __half2 r7 = xh[(size_t)e7.x * 32 + lane];
            float2 x0 = __half22float2(r0), x1 = __half22float2(r1);
            float2 x2 = __half22float2(r2), x3 = __half22float2(r3);
            float2 x4 = __half22float2(r4), x5 = __half22float2(r5);
            float2 x6 = __half22float2(r6), x7 = __half22float2(r7);
            float c0 = __int_as_float(e0.y), c1 = __int_as_float(e1.y);
            float c2 = __int_as_float(e2.y), c3 = __int_as_float(e3.y);
            float c4 = __int_as_float(e4.y), c5 = __int_as_float(e5.y);
            float c6 = __int_as_float(e6.y), c7 = __int_as_float(e7.y);
            a.x = fmaf(x0.x, c0, a.x); a.y = fmaf(x0.y, c0, a.y);
            a.x = fmaf(x1.x, c1, a.x); a.y = fmaf(x1.y, c1, a.y);
            a.x = fmaf(x2.x, c2, a.x); a.y = fmaf(x2.y, c2, a.y);
            a.x = fmaf(x3.x, c3, a.x); a.y = fmaf(x3.y, c3, a.y);
            a.x = fmaf(x4.x, c4, a.x); a.y = fmaf(x4.y, c4, a.y);
            a.x = fmaf(x5.x, c5, a.x); a.y = fmaf(x5.y, c5, a.y);
            a.x = fmaf(x6.x, c6, a.x); a.y = fmaf(x6.y, c6, a.y);
            a.x = fmaf(x7.x, c7, a.x); a.y = fmaf(x7.y, c7, a.y);
        }
        for (; p + 1 < pe; p += 2) {
            int2 e0 = ed[p], e1 = ed[p + 1];
            float2 x0 = __half22float2(xh[(size_t)e0.x * 32 + lane]);
            float2 x1 = __half22float2(xh[(size_t)e1.x * 32 + lane]);
            float c0 = __int_as_float(e0.y), c1 = __int_as_float(e1.y);
            a.x = fmaf(x0.x, c0, a.x); a.y = fmaf(x0.y, c0, a.y);
            a.x = fmaf(x1.x, c1, a.x); a.y = fmaf(x1.y, c1, a.y);
        }
        if (p < pe) {
            int2 e0 = ed[p];
            float2 x0 = __half22float2(xh[(size_t)e0.x * 32 + lane]);
            float c0 = __int_as_float(e0.y);
            a.x = fmaf(x0.x, c0, a.x); a.y = fmaf(x0.y, c0, a.y);
        }
        a.x *= dvn.x; a.y *= dvn.x;              // apply dinv1[dst] once to the whole sum

        float2 bb = b1[lane];
        float h0 = fmaxf(a.x + bb.x, 0.f);
        float h1 = fmaxf(a.y + bb.y, 0.f);
        f.x += h0; f.y += h1;
        float2 wv = w2[lane];
        float hw = h0 * wv.x + h1 * wv.y;
#pragma unroll
        for (int o = 16; o; o >>= 1) hw += __shfl_xor_sync(0xffffffffu, hw, o);
        if (lane == 0) g_hw2[v * MAXN + n] = make_float2(hw, dvn.y);
    }
    float2* fo = reinterpret_cast<float2*>(out + N + (size_t)n * NHID);
    fo[lane] = f;
}

// ---------------- conv2 aggregate -> x_flat (warp per node) ----------------
__global__ __launch_bounds__(256) void k_out(
    const float* __restrict__ b2a, const float* __restrict__ b2b, const float* __restrict__ b2c,
    float* __restrict__ out, int N)
{
    int n = (blockIdx.x * 256 + threadIdx.x) >> 5;
    int lane = threadIdx.x & 31;
    if (n >= N) return;
    float acc0 = 0.f, acc1 = 0.f, acc2 = 0.f;
    {
        int p0 = g_rowstart[0 * (MAXN + 1) + n];
        int p1 = g_rowstart[0 * (MAXN + 1) + n + 1];
        const int2* ed = g_ed1;
        for (int p = p0 + lane; p < p1; p += 32) {
            float2 hd = g_hw2[0 * MAXN + ed[p].x];
            acc0 += hd.x * hd.y;
        }
    }
    {
        int p0 = g_rowstart[1 * (MAXN + 1) + n];
        int p1 = g_rowstart[1 * (MAXN + 1) + n + 1];
        const int2* ed = g_ed1 + (size_t)MAXE;
        for (int p = p0 + lane; p < p1; p += 32) {
            float2 hd = g_hw2[1 * MAXN + ed[p].x];
            acc1 += hd.x * hd.y;
        }
    }
    {
        int p0 = g_rowstart[2 * (MAXN + 1) + n];
        int p1 = g_rowstart[2 * (MAXN + 1) + n + 1];
        const int2* ed = g_ed1 + (size_t)2 * MAXE;
        for (int p = p0 + lane; p < p1; p += 32) {
            float2 hd = g_hw2[2 * MAXN + ed[p].x];
            acc2 += hd.x * hd.y;
        }
    }
#pragma unroll
    for (int o = 16; o; o >>= 1) {
        acc0 += __shfl_xor_sync(0xffffffffu, acc0, o);
        acc1 += __shfl_xor_sync(0xffffffffu, acc1, o);
        acc2 += __shfl_xor_sync(0xffffffffu, acc2, o);
    }
    if (lane == 0) {
        float2 s0 = g_hw2[0 * MAXN + n];
        float2 s1 = g_hw2[1 * MAXN + n];
        float2 s2 = g_hw2[2 * MAXN + n];
        float t = s0.y * (acc0 + s0.y * s0.x) + b2a[0]
                + s1.y * (acc1 + s1.y * s1.x) + b2b[0]
                + s2.y * (acc2 + s2.y * s2.x) + b2c[0];
        out[n] = t;
    }
}

// ---------------- launch ----------------
extern "C" void kernel_launch(void* const* d_in, const int* in_sizes, int n_in,
                              void* d_out, int out_size)
{
    const float* x = (const float*)d_in[0];
    const int* ei0 = (const int*)d_in[1];
    const int* ei1 = (const int*)d_in[2];
    const int* ei2 = (const int*)d_in[3];
    const float* ew0 = (const float*)d_in[4];
    const float* ew1 = (const float*)d_in[5];
    const float* ew2 = (const float*)d_in[6];
    const float* W1a = (const float*)d_in[7];
    const float* b1a = (const float*)d_in[8];
    const float* W2a = (const float*)d_in[9];
    const float* b2a = (const float*)d_in[10];
    const float* W1b = (const float*)d_in[11];
    const float* b1b = (const float*)d_in[12];
    const float* W2b = (const float*)d_in[13];
    const float* b2b = (const float*)d_in[14];
    const float* W1c = (const float*)d_in[15];
    const float* b1c = (const float*)d_in[16];
    const float* W2c = (const float*)d_in[17];
    const float* b2c = (const float*)d_in[18];

    int N = in_sizes[0] / FIN;
    int E = in_sizes[1] / 2;
    float* out = (float*)d_out;

    int nb_n = (N + 255) / 256;
    int eb   = (E + 255) / 256;
    int nchunk = (N + 1023) / 1024;

    k_init<<<dim3(nb_n, 3), 256>>>(N);
    k_deg<<<dim3(eb, 3), 256>>>(ei0, ei1, ei2, ew0, ew1, ew2, E);
    k_scanA<<<dim3(nchunk, 3), 1024>>>(N);
    k_scanB<<<3, 64>>>(nchunk, N, E);
    k_scanC<<<dim3(nchunk, 3), 1024>>>(N);
    k_gemm<<<dim3((N + 127) / 128, 3), 256>>>(x, W1a, W1b, W1c, N);   // needs dinv (epilogue scale)
    k_fill<<<dim3(eb, 3), 256>>>(ei0, ei1, ei2, ew0, ew1, ew2, E);
    k_agg<<<(N + 7) / 8, 256>>>(b1a, b1b, b1c, W2a, W2b, W2c, out, N);
    k_out<<<(N + 7) / 8, 256>>>(b2a, b2b, b2c, out, N);
}